// round 13
// baseline (speedup 1.0000x reference)
#include <cuda_runtime.h>
#include <stdint.h>

#define HH 1024
#define WW 1024
#define BB 8
#define CC 3
#define HW (HH*WW)
#define SPITCH 1040
#define SEG 32
#define SEGROWS 32

// scratch (__device__ globals; no allocation allowed)
__device__ float4  g_packed[(size_t)BB*HW];         // (r,g,b,1) fp32  128 MB
__device__ uint8_t g_R[(size_t)BB*HW];              // floor(depth) 8 MB
__device__ float   g_cnt[2u*BB*HW];                 // 64 MB
__device__ float   g_segsum[16*SEG*4*WW];           // 8 MB

// packed f32x2 sign constants: (+1,+1) and (-1,-1)
#define SPLUS  0x3F8000003F800000ull
#define SMINUS 0xBF800000BF800000ull

// ---------- helpers ----------
__device__ __forceinline__ float4 z4() { return make_float4(0,0,0,0); }
__device__ __forceinline__ float4 f4add(float4 a, float4 b){
    return make_float4(a.x+b.x, a.y+b.y, a.z+b.z, a.w+b.w);
}
__device__ __forceinline__ void f4fma(float4& a, float s, float4 p){
    a.x = fmaf(s, p.x, a.x); a.y = fmaf(s, p.y, a.y);
    a.z = fmaf(s, p.z, a.z); a.w = fmaf(s, p.w, a.w);
}
__device__ __forceinline__ void padd(float4& a, float s,
                                     const float4* __restrict__ pb,
                                     int row, int col) {
    f4fma(a, s, __ldg(pb + (size_t)row*WW + col));
}

__device__ __forceinline__ float4 unpack2(unsigned long long a01,
                                          unsigned long long a23) {
    return make_float4(__uint_as_float((uint32_t)a01),
                       __uint_as_float((uint32_t)(a01 >> 32)),
                       __uint_as_float((uint32_t)a23),
                       __uint_as_float((uint32_t)(a23 >> 32)));
}

__device__ __forceinline__ float4 warp_iscan4(float4 v) {
    int lane = threadIdx.x & 31;
    #pragma unroll
    for (int o = 1; o < 32; o <<= 1) {
        float ax = __shfl_up_sync(0xffffffffu, v.x, o);
        float ay = __shfl_up_sync(0xffffffffu, v.y, o);
        float az = __shfl_up_sync(0xffffffffu, v.z, o);
        float aw = __shfl_up_sync(0xffffffffu, v.w, o);
        if (lane >= o) { v.x += ax; v.y += ay; v.z += az; v.w += aw; }
    }
    return v;
}

// One gather site: predication INSIDE the asm (no branches), immediate offset,
// fp32x2 packed FMA on the raw 16B pixel (no conversions).
#define SITE(A01, A23, MV, SG, IMM) \
    asm("{\n\t" \
        ".reg .pred pq;\n\t" \
        ".reg .b64 vq0, vq1;\n\t" \
        "setp.ne.u32 pq, %2, 0;\n\t" \
        "@pq ld.global.nc.v2.u64 {vq0, vq1}, [%3 + %4];\n\t" \
        "@pq fma.rn.f32x2 %0, vq0, %5, %0;\n\t" \
        "@pq fma.rn.f32x2 %1, vq1, %5, %1;\n\t" \
        "}" \
        : "+l"(A01), "+l"(A23) \
        : "r"(MV), "l"(bp), "n"(IMM), "l"(SG))

// all 8 corner sites for radius r (r must be a literal 0..7)
#define ROWR(r) do { \
    const uint32_t mA = sM[x + 16 + 2*(r)]; \
    const uint32_t mD = sM[x + 15 - 2*(r)]; \
    SITE(dl01, dl23, mA & (1u << (r)),       SP,   (r)*16384 + 32*(r)); \
    SITE(dl01, dl23, mB & (1u << (r)),       SM_,  (r)*16384 - 16); \
    SITE(dl01, dl23, mA & (1u << (8+(r))),   SM_, -((r)+1)*16384 + 32*(r)); \
    SITE(dl01, dl23, mB & (1u << (8+(r))),   SP,  -((r)+1)*16384 - 16); \
    SITE(dr01, dr23, mX & (1u << (r)),       SP,   (r)*16384); \
    SITE(dr01, dr23, mX & (1u << (8+(r))),   SM_, -((r)+1)*16384); \
    SITE(dr01, dr23, mD & (1u << (r)),       SM_,  (r)*16384 - 32*(r) - 16); \
    SITE(dr01, dr23, mD & (1u << (8+(r))),   SP,  -((r)+1)*16384 - 32*(r) - 16); \
} while (0)

// ---------- dummy kernels: rotate profiler capture slot onto k_rowscan ----------
__global__ void k_nop1() {}
__global__ void k_nop2() {}

// ---------- K0: pack channels (r,g,b,1) fp32 + depth -> uint8 radius ----------
__global__ __launch_bounds__(256)
void k_prep(const float* __restrict__ image, const float* __restrict__ depth) {
    const size_t i = (size_t)blockIdx.x*1024 + threadIdx.x*4;
    const size_t b = i / HW;
    const size_t o = i - b*HW;
    const float* p = image + b*CC*HW + o;
    float4 r = __ldg((const float4*)(p));
    float4 g = __ldg((const float4*)(p + HW));
    float4 bl= __ldg((const float4*)(p + 2*HW));
    float4* dst = g_packed + i;
    dst[0] = make_float4(r.x, g.x, bl.x, 1.f);
    dst[1] = make_float4(r.y, g.y, bl.y, 1.f);
    dst[2] = make_float4(r.z, g.z, bl.z, 1.f);
    dst[3] = make_float4(r.w, g.w, bl.w, 1.f);

    float4 d = __ldg((const float4*)(depth + i));
    uchar4 v;
    v.x = (uint8_t)(int)d.x; v.y = (uint8_t)(int)d.y;
    v.z = (uint8_t)(int)d.z; v.w = (uint8_t)(int)d.w;
    *(uchar4*)(g_R + i) = v;
}

// ---------- generic border delta (proven path, fp32 gather) ----------
__device__ void generic_delta(int y, int x, const uint8_t sR[16][SPITCH],
                              const float4* __restrict__ pb,
                              float4& dl, float4& dr) {
    for (int r = 0; r < 8; ++r) {
        const int t0 = (y > 0) ? y + r : 0;
        const int t1 = (y > 0) ? y + r : r;
        const int brow = y - r - 1;
        const int a0 = (x > 0) ? x + 2*r : 0;
        const int a1 = (x > 0) ? x + 2*r : 2*r;
        const int xB = x - 1;
        const int xD = x - 2*r - 1;
        for (int yy = t0; yy <= t1; ++yy) {
            const int idx = yy - y + 8;
            for (int a = a0; a <= a1; ++a)
                if (a < WW && sR[idx][a] == r) padd(dl,  1.f, pb, yy, a);
            if (xB >= 0 && sR[idx][xB] == r)   padd(dl, -1.f, pb, yy, xB);
            if (sR[idx][x] == r)               padd(dr,  1.f, pb, yy, x);
            if (xD >= 0 && sR[idx][xD] == r)   padd(dr, -1.f, pb, yy, xD);
        }
        if (brow >= 0) {
            const int idx = 7 - r;
            for (int a = a0; a <= a1; ++a)
                if (a < WW && sR[idx][a] == r) padd(dl, -1.f, pb, brow, a);
            if (xB >= 0 && sR[idx][xB] == r)   padd(dl,  1.f, pb, brow, xB);
            if (sR[idx][x] == r)               padd(dr, -1.f, pb, brow, x);
            if (xD >= 0 && sR[idx][xD] == r)   padd(dr,  1.f, pb, brow, xD);
        }
    }
}

// ---------- K1: asm-predicated imm-offset gather + chained row scan ----------
__global__ __launch_bounds__(256)
void k_rowscan(float* __restrict__ out) {
    __shared__ uint8_t  sR[16][SPITCH];
    // linear source masks: sM[col + 16]; zero pads at [0,16) and [1040,1056)
    // bit r   : R(y+r,   col) == r   (top class)
    // bit 8+r : R(y-r-1, col) == r   (bottom class)
    __shared__ uint32_t sM[1056];
    __shared__ float4 wtl[9], wtr[9];   // [8] = block total

    const int y = blockIdx.x;
    const int b = blockIdx.y;
    const int t = threadIdx.x;
    const int lane = t & 31, wid = t >> 5;

    // ---- fill: thread t owns column quad [4t, 4t+3] across all 16 window rows ----
    {
        const uint8_t* rb = g_R + (size_t)b*HW;
        uint32_t mc0 = 0, mc1 = 0, mc2 = 0, mc3 = 0;
        #pragma unroll
        for (int rr = 0; rr < 16; ++rr) {
            const int ar = y - 8 + rr;
            uchar4 v4 = make_uchar4(255,255,255,255);
            if (ar >= 0 && ar < HH)
                v4 = __ldg((const uchar4*)(rb + (size_t)ar*WW + 4*t));
            *(uchar4*)&sR[rr][4*t] = v4;
            if (rr >= 8) {
                const uint32_t bitc = 1u << (rr - 8);
                if (v4.x == rr - 8) mc0 |= bitc;
                if (v4.y == rr - 8) mc1 |= bitc;
                if (v4.z == rr - 8) mc2 |= bitc;
                if (v4.w == rr - 8) mc3 |= bitc;
            } else {
                const uint32_t bitc = 1u << (8 + 7 - rr);
                if (v4.x == 7 - rr) mc0 |= bitc;
                if (v4.y == 7 - rr) mc1 |= bitc;
                if (v4.z == 7 - rr) mc2 |= bitc;
                if (v4.w == 7 - rr) mc3 |= bitc;
            }
        }
        sM[4*t + 16] = mc0;
        sM[4*t + 17] = mc1;
        sM[4*t + 18] = mc2;
        sM[4*t + 19] = mc3;
        if (t < 16) { sM[t] = 0u; sM[1040 + t] = 0u; }
    }
    __syncthreads();

    const float4* pb4 = g_packed + (size_t)b*HW;

    const int vbL = b, vbR = BB + b;
    float* cL = g_cnt + (size_t)vbL*HW + (size_t)y*WW;
    float* cR = g_cnt + (size_t)vbR*HW + (size_t)y*WW;
    float* oL = out + (size_t)vbL*CC*HW + (size_t)y*WW;
    float* oR = out + (size_t)vbR*CC*HW + (size_t)y*WW;

    float4 carL = z4(), carR = z4();
    const unsigned long long SP = SPLUS, SM_ = SMINUS;

    #pragma unroll 1
    for (int s = 0; s < 4; ++s) {
        const int x = 256*s + t;        // lane-consecutive
        float4 dl, dr;

        if (y > 0 && x > 0) {
            unsigned long long dl01 = 0, dl23 = 0, dr01 = 0, dr23 = 0;
            const char* bp = (const char*)(pb4 + ((size_t)y*WW + x));
            const uint32_t mB = sM[x + 15];
            const uint32_t mX = sM[x + 16];
            ROWR(0); ROWR(1); ROWR(2); ROWR(3);
            ROWR(4); ROWR(5); ROWR(6); ROWR(7);
            dl = unpack2(dl01, dl23);
            dr = unpack2(dr01, dr23);
        } else {
            dl = z4(); dr = z4();
            generic_delta(y, x, sR, pb4, dl, dr);
        }

        // ---- block-wide inclusive scan of this 256-wide segment ----
        float4 il = warp_iscan4(dl);
        float4 ir = warp_iscan4(dr);
        if (lane == 31) { wtl[wid] = il; wtr[wid] = ir; }
        __syncthreads();
        if (t == 0) {
            float4 ssum = z4();
            #pragma unroll
            for (int w = 0; w < 8; ++w) { float4 tt = wtl[w]; wtl[w] = ssum; ssum = f4add(ssum, tt); }
            wtl[8] = ssum;
            ssum = z4();
            #pragma unroll
            for (int w = 0; w < 8; ++w) { float4 tt = wtr[w]; wtr[w] = ssum; ssum = f4add(ssum, tt); }
            wtr[8] = ssum;
        }
        __syncthreads();
        const float4 tl = f4add(carL, f4add(wtl[wid], il));
        const float4 tr = f4add(carR, f4add(wtr[wid], ir));

        cL[x]        = tl.w;
        cR[x]        = tr.w;
        oL[x]        = tl.x;
        oL[x +   HW] = tl.y;
        oL[x + 2*HW] = tl.z;
        oR[x]        = tr.x;
        oR[x +   HW] = tr.y;
        oR[x + 2*HW] = tr.z;

        carL = f4add(carL, wtl[8]);
        carR = f4add(carR, wtr[8]);
        __syncthreads();
    }
}

// ---------- K2a: per-segment column sums (plane-split) ----------
__global__ __launch_bounds__(256)
void k_colsum(const float* __restrict__ out) {
    const int plane = blockIdx.x;
    const int seg   = blockIdx.y;
    const int vb    = blockIdx.z;
    const int xc    = threadIdx.x * 4;

    const float* src = (plane == 0)
        ? g_cnt + (size_t)vb*HW
        : out + ((size_t)vb*CC + (plane-1))*HW;

    float4 s = z4();
    const int y0 = seg * SEGROWS;
    #pragma unroll 8
    for (int yy = 0; yy < SEGROWS; ++yy)
        s = f4add(s, __ldg((const float4*)(src + (size_t)(y0 + yy)*WW + xc)));

    *(float4*)(g_segsum + (size_t)(((vb*SEG + seg)*4 + plane))*WW + xc) = s;
}

// ---------- K2b: column scan (seeded) + finalize ----------
__global__ __launch_bounds__(128)
void k_colscan_final(float* __restrict__ out) {
    const int seg = blockIdx.y;
    const int vb  = blockIdx.z;
    const int xc  = blockIdx.x*512 + threadIdx.x*4;

    float4 r0 = z4(), r1 = z4(), r2 = z4(), r3 = z4();
    for (int s = 0; s < seg; ++s) {
        const float* ss = g_segsum + (size_t)((vb*SEG + s)*4)*WW + xc;
        r0 = f4add(r0, __ldg((const float4*)(ss + 0*WW)));
        r1 = f4add(r1, __ldg((const float4*)(ss + 1*WW)));
        r2 = f4add(r2, __ldg((const float4*)(ss + 2*WW)));
        r3 = f4add(r3, __ldg((const float4*)(ss + 3*WW)));
    }

    const float* p0 = g_cnt + (size_t)vb*HW + xc;
    float* p1 = out + ((size_t)vb*CC + 0)*HW + xc;
    float* p2 = p1 + HW;
    float* p3 = p1 + 2*HW;

    const int y0 = seg * SEGROWS;
    #pragma unroll 2
    for (int yy = 0; yy < SEGROWS; ++yy) {
        const size_t o = (size_t)(y0 + yy)*WW;
        r0 = f4add(r0, __ldg((const float4*)(p0 + o)));
        r1 = f4add(r1, __ldg((const float4*)(p1 + o)));
        r2 = f4add(r2, __ldg((const float4*)(p2 + o)));
        r3 = f4add(r3, __ldg((const float4*)(p3 + o)));

        float4 inv;
        inv.x = __fdividef(1.0f, fmaxf(r0.x, 1.0f));
        inv.y = __fdividef(1.0f, fmaxf(r0.y, 1.0f));
        inv.z = __fdividef(1.0f, fmaxf(r0.z, 1.0f));
        inv.w = __fdividef(1.0f, fmaxf(r0.w, 1.0f));

        *(float4*)(p1 + o) = make_float4(__saturatef(r1.x*inv.x), __saturatef(r1.y*inv.y),
                                         __saturatef(r1.z*inv.z), __saturatef(r1.w*inv.w));
        *(float4*)(p2 + o) = make_float4(__saturatef(r2.x*inv.x), __saturatef(r2.y*inv.y),
                                         __saturatef(r2.z*inv.z), __saturatef(r2.w*inv.w));
        *(float4*)(p3 + o) = make_float4(__saturatef(r3.x*inv.x), __saturatef(r3.y*inv.y),
                                         __saturatef(r3.z*inv.z), __saturatef(r3.w*inv.w));
    }
}

extern "C" void kernel_launch(void* const* d_in, const int* in_sizes, int n_in,
                              void* d_out, int out_size) {
    const float* image = (const float*)d_in[0];   // (8,3,1024,1024) f32
    const float* depth = (const float*)d_in[1];   // (8,1024,1024)   f32
    float* out = (float*)d_out;                   // [left(8,3,H,W), right(8,3,H,W)]

    // two no-ops rotate the ncu capture slot (launch #64, 64 mod 6 = 4)
    // onto k_rowscan at position 4.
    k_nop1<<<1, 32>>>();
    k_nop2<<<1, 32>>>();
    k_prep<<<BB*HW/1024, 256>>>(image, depth);
    k_rowscan<<<dim3(HH, BB), 256>>>(out);
    k_colsum<<<dim3(4, SEG, 16), 256>>>(out);
    k_colscan_final<<<dim3(2, SEG, 16), 128>>>(out);
}

// round 14
// speedup vs baseline: 1.5905x; 1.5905x over previous
#include <cuda_runtime.h>
#include <stdint.h>

#define HH 1024
#define WW 1024
#define BB 8
#define CC 3
#define HW (HH*WW)
#define SPITCH 1040
#define SEG 32
#define SEGROWS 32

// scratch (__device__ globals; no allocation allowed)
__device__ float4  g_packed[(size_t)BB*HW];         // (r,g,b,1) fp32  128 MB
__device__ uint8_t g_R[(size_t)BB*HW];              // floor(depth) 8 MB
__device__ float   g_cnt[2u*BB*HW];                 // 64 MB
__device__ float   g_segsum[16*SEG*4*WW];           // 8 MB

// dynamic smem layout (bytes)
#define SM_SR    0                    // uint8 [16][1040]      = 16640
#define SM_H     16640                // float4 [8][1056]      = 135168 -> 151808
#define SM_G     151808               // float4 [1056]         = 16896  -> 168704
#define SM_WT    168704               // float4 [2][32]        = 1024   -> 169728
#define SM_TOTAL 169728

// ---------- helpers ----------
__device__ __forceinline__ float4 z4() { return make_float4(0,0,0,0); }
__device__ __forceinline__ float4 f4add(float4 a, float4 b){
    return make_float4(a.x+b.x, a.y+b.y, a.z+b.z, a.w+b.w);
}
__device__ __forceinline__ float4 f4sub(float4 a, float4 b){
    return make_float4(a.x-b.x, a.y-b.y, a.z-b.z, a.w-b.w);
}
__device__ __forceinline__ void f4fma(float4& a, float s, float4 p){
    a.x = fmaf(s, p.x, a.x); a.y = fmaf(s, p.y, a.y);
    a.z = fmaf(s, p.z, a.z); a.w = fmaf(s, p.w, a.w);
}
__device__ __forceinline__ void padd(float4& a, float s,
                                     const float4* __restrict__ pb,
                                     int row, int col) {
    f4fma(a, s, __ldg(pb + (size_t)row*WW + col));
}

__device__ __forceinline__ float4 warp_iscan4(float4 v) {
    int lane = threadIdx.x & 31;
    #pragma unroll
    for (int o = 1; o < 32; o <<= 1) {
        float ax = __shfl_up_sync(0xffffffffu, v.x, o);
        float ay = __shfl_up_sync(0xffffffffu, v.y, o);
        float az = __shfl_up_sync(0xffffffffu, v.z, o);
        float aw = __shfl_up_sync(0xffffffffu, v.w, o);
        if (lane >= o) { v.x += ax; v.y += ay; v.z += az; v.w += aw; }
    }
    return v;
}

// ---------- dummy kernels: rotate profiler capture slot onto k_rowscan ----------
__global__ void k_nop1() {}
__global__ void k_nop2() {}

// ---------- K0: pack channels (r,g,b,1) fp32 + depth -> uint8 radius ----------
__global__ __launch_bounds__(256)
void k_prep(const float* __restrict__ image, const float* __restrict__ depth) {
    const size_t i = (size_t)blockIdx.x*1024 + threadIdx.x*4;
    const size_t b = i / HW;
    const size_t o = i - b*HW;
    const float* p = image + b*CC*HW + o;
    float4 r = __ldg((const float4*)(p));
    float4 g = __ldg((const float4*)(p + HW));
    float4 bl= __ldg((const float4*)(p + 2*HW));
    float4* dst = g_packed + i;
    dst[0] = make_float4(r.x, g.x, bl.x, 1.f);
    dst[1] = make_float4(r.y, g.y, bl.y, 1.f);
    dst[2] = make_float4(r.z, g.z, bl.z, 1.f);
    dst[3] = make_float4(r.w, g.w, bl.w, 1.f);

    float4 d = __ldg((const float4*)(depth + i));
    uchar4 v;
    v.x = (uint8_t)(int)d.x; v.y = (uint8_t)(int)d.y;
    v.z = (uint8_t)(int)d.z; v.w = (uint8_t)(int)d.w;
    *(uchar4*)(g_R + i) = v;
}

// ---------- generic border delta (proven path, fp32 gather) ----------
__device__ void generic_delta(int y, int x, const uint8_t (*sR)[SPITCH],
                              const float4* __restrict__ pb,
                              float4& dl, float4& dr) {
    for (int r = 0; r < 8; ++r) {
        const int t0 = (y > 0) ? y + r : 0;
        const int t1 = (y > 0) ? y + r : r;
        const int brow = y - r - 1;
        const int a0 = (x > 0) ? x + 2*r : 0;
        const int a1 = (x > 0) ? x + 2*r : 2*r;
        const int xB = x - 1;
        const int xD = x - 2*r - 1;
        for (int yy = t0; yy <= t1; ++yy) {
            const int idx = yy - y + 8;
            for (int a = a0; a <= a1; ++a)
                if (a < WW && sR[idx][a] == r) padd(dl,  1.f, pb, yy, a);
            if (xB >= 0 && sR[idx][xB] == r)   padd(dl, -1.f, pb, yy, xB);
            if (sR[idx][x] == r)               padd(dr,  1.f, pb, yy, x);
            if (xD >= 0 && sR[idx][xD] == r)   padd(dr, -1.f, pb, yy, xD);
        }
        if (brow >= 0) {
            const int idx = 7 - r;
            for (int a = a0; a <= a1; ++a)
                if (a < WW && sR[idx][a] == r) padd(dl, -1.f, pb, brow, a);
            if (xB >= 0 && sR[idx][xB] == r)   padd(dl,  1.f, pb, brow, xB);
            if (sR[idx][x] == r)               padd(dr, -1.f, pb, brow, x);
            if (xD >= 0 && sR[idx][xD] == r)   padd(dr,  1.f, pb, brow, xD);
        }
    }
}

// ---------- K1: H-factorized gather, 1 row per 1024-thread block ----------
// H_r(c) = [R(y+r,c)==r]*pix(y+r,c) - [R(y-r-1,c)==r]*pix(y-r-1,c); G = sum_r H_r
// dl(x) = sum_r H_r(x+2r) - G(x-1);   dr(x) = G(x) - sum_r H_r(x-2r-1)
__global__ __launch_bounds__(1024, 1)
void k_rowscan(float* __restrict__ out) {
    extern __shared__ char smem[];
    uint8_t (*sR)[SPITCH] = (uint8_t(*)[SPITCH])(smem + SM_SR);
    float4* sH  = (float4*)(smem + SM_H);     // [r*1056 + col+16]
    float4* sG  = (float4*)(smem + SM_G);     // [col+16]
    float4* wtL = (float4*)(smem + SM_WT);
    float4* wtR = wtL + 32;

    const int y = blockIdx.x;
    const int b = blockIdx.y;
    const int t = threadIdx.x;                // t == column x
    const int lane = t & 31, wid = t >> 5;

    // ---- phase 1: fill sR window (16 rows) + zero H/G pads ----
    {
        const uint8_t* rb = g_R + (size_t)b*HW;
        for (int i = t; i < 16*256; i += 1024) {   // quads cover cols 0..1023
            const int rr = i >> 8;
            const int c4 = (i & 255) * 4;
            const int ar = y - 8 + rr;
            uchar4 v = make_uchar4(255,255,255,255);
            if (ar >= 0 && ar < HH)
                v = __ldg((const uchar4*)(rb + (size_t)ar*WW + c4));
            *(uchar4*)&sR[rr][c4] = v;
        }
        // pad cols 1024..1039 of sR (generic path may index a<WW only; safe anyway)
        if (t < 16*4) {
            const int rr = t >> 2;
            *(uchar4*)&sR[rr][1024 + (t & 3)*4] = make_uchar4(255,255,255,255);
        }
        if (t < 288) {     // zero H pads (r<8) and G pads (r==8): cols [0,16)+[1040,1056)
            const int r = t >> 5, j = t & 31;
            const int col = (j < 16) ? j : (1024 + j);
            if (r < 8) sH[r*1056 + col] = z4();
            else       sG[col] = z4();
        }
    }
    __syncthreads();

    const float4* pb4 = g_packed + (size_t)b*HW;
    const float4* colP = pb4 + (size_t)y*WW + t;

    // ---- phase 2: per-column H_r + G (the ONLY gather sites: 16 predicated LDG) ----
    float4 G = z4();
    #pragma unroll
    for (int r = 0; r < 8; ++r) {
        float4 h = z4();
        const bool bt = (sR[8 + r][t] == r);      // row y+r
        const bool bb = (sR[7 - r][t] == r);      // row y-r-1
        if (bt) h = __ldg(colP + r*WW);
        if (bb) { const float4 p = __ldg(colP - (r+1)*WW); h = f4sub(h, p); }
        sH[r*1056 + t + 16] = h;
        G = f4add(G, h);
    }
    sG[t + 16] = G;
    __syncthreads();

    // ---- phase 3: assemble deltas from smem (no gmem, conflict-free LDS.128) ----
    float4 dl, dr;
    if (y > 0 && t > 0) {
        dl = f4sub(z4(), sG[t + 15]);   // -G(x-1)
        dr = G;                          // +G(x) (own register)
        #pragma unroll
        for (int r = 0; r < 8; ++r) {
            dl = f4add(dl, sH[r*1056 + t + 16 + 2*r]);   // A: +H_r(x+2r)
            dr = f4sub(dr, sH[r*1056 + t + 15 - 2*r]);   // D: -H_r(x-2r-1)
        }
    } else {
        dl = z4(); dr = z4();
        generic_delta(y, t, (const uint8_t(*)[SPITCH])sR, pb4, dl, dr);
    }

    // ---- phase 4: 1024-wide inclusive scan (warp scan + 32-total scan) ----
    float4 il = warp_iscan4(dl);
    float4 ir = warp_iscan4(dr);
    if (lane == 31) { wtL[wid] = il; wtR[wid] = ir; }
    __syncthreads();
    if (t < 32) {
        float4 v = wtL[t];
        float4 s = warp_iscan4(v);
        wtL[t] = f4sub(s, v);            // exclusive offsets
    } else if (t < 64) {
        const int u = t - 32;
        float4 v = wtR[u];
        float4 s = warp_iscan4(v);
        wtR[u] = f4sub(s, v);
    }
    __syncthreads();
    const float4 tl = f4add(wtL[wid], il);
    const float4 tr = f4add(wtR[wid], ir);

    // ---- stores: cnt (.w) -> g_cnt, channels -> d_out planes ----
    const int vbL = b, vbR = BB + b;
    const size_t rowoff = (size_t)y*WW + t;
    g_cnt[(size_t)vbL*HW + rowoff] = tl.w;
    g_cnt[(size_t)vbR*HW + rowoff] = tr.w;

    float* oL = out + (size_t)vbL*CC*HW + rowoff;
    float* oR = out + (size_t)vbR*CC*HW + rowoff;
    oL[0]      = tl.x;
    oL[HW]     = tl.y;
    oL[2*HW]   = tl.z;
    oR[0]      = tr.x;
    oR[HW]     = tr.y;
    oR[2*HW]   = tr.z;
}

// ---------- K2a: per-segment column sums (plane-split) ----------
__global__ __launch_bounds__(256)
void k_colsum(const float* __restrict__ out) {
    const int plane = blockIdx.x;
    const int seg   = blockIdx.y;
    const int vb    = blockIdx.z;
    const int xc    = threadIdx.x * 4;

    const float* src = (plane == 0)
        ? g_cnt + (size_t)vb*HW
        : out + ((size_t)vb*CC + (plane-1))*HW;

    float4 s = z4();
    const int y0 = seg * SEGROWS;
    #pragma unroll 8
    for (int yy = 0; yy < SEGROWS; ++yy)
        s = f4add(s, __ldg((const float4*)(src + (size_t)(y0 + yy)*WW + xc)));

    *(float4*)(g_segsum + (size_t)(((vb*SEG + seg)*4 + plane))*WW + xc) = s;
}

// ---------- K2b: column scan (seeded) + finalize ----------
__global__ __launch_bounds__(128)
void k_colscan_final(float* __restrict__ out) {
    const int seg = blockIdx.y;
    const int vb  = blockIdx.z;
    const int xc  = blockIdx.x*512 + threadIdx.x*4;

    float4 r0 = z4(), r1 = z4(), r2 = z4(), r3 = z4();
    for (int s = 0; s < seg; ++s) {
        const float* ss = g_segsum + (size_t)((vb*SEG + s)*4)*WW + xc;
        r0 = f4add(r0, __ldg((const float4*)(ss + 0*WW)));
        r1 = f4add(r1, __ldg((const float4*)(ss + 1*WW)));
        r2 = f4add(r2, __ldg((const float4*)(ss + 2*WW)));
        r3 = f4add(r3, __ldg((const float4*)(ss + 3*WW)));
    }

    const float* p0 = g_cnt + (size_t)vb*HW + xc;
    float* p1 = out + ((size_t)vb*CC + 0)*HW + xc;
    float* p2 = p1 + HW;
    float* p3 = p1 + 2*HW;

    const int y0 = seg * SEGROWS;
    #pragma unroll 2
    for (int yy = 0; yy < SEGROWS; ++yy) {
        const size_t o = (size_t)(y0 + yy)*WW;
        r0 = f4add(r0, __ldg((const float4*)(p0 + o)));
        r1 = f4add(r1, __ldg((const float4*)(p1 + o)));
        r2 = f4add(r2, __ldg((const float4*)(p2 + o)));
        r3 = f4add(r3, __ldg((const float4*)(p3 + o)));

        float4 inv;
        inv.x = __fdividef(1.0f, fmaxf(r0.x, 1.0f));
        inv.y = __fdividef(1.0f, fmaxf(r0.y, 1.0f));
        inv.z = __fdividef(1.0f, fmaxf(r0.z, 1.0f));
        inv.w = __fdividef(1.0f, fmaxf(r0.w, 1.0f));

        *(float4*)(p1 + o) = make_float4(__saturatef(r1.x*inv.x), __saturatef(r1.y*inv.y),
                                         __saturatef(r1.z*inv.z), __saturatef(r1.w*inv.w));
        *(float4*)(p2 + o) = make_float4(__saturatef(r2.x*inv.x), __saturatef(r2.y*inv.y),
                                         __saturatef(r2.z*inv.z), __saturatef(r2.w*inv.w));
        *(float4*)(p3 + o) = make_float4(__saturatef(r3.x*inv.x), __saturatef(r3.y*inv.y),
                                         __saturatef(r3.z*inv.z), __saturatef(r3.w*inv.w));
    }
}

extern "C" void kernel_launch(void* const* d_in, const int* in_sizes, int n_in,
                              void* d_out, int out_size) {
    const float* image = (const float*)d_in[0];   // (8,3,1024,1024) f32
    const float* depth = (const float*)d_in[1];   // (8,1024,1024)   f32
    float* out = (float*)d_out;                   // [left(8,3,H,W), right(8,3,H,W)]

    // deterministic, idempotent: raise dynamic-smem cap for the big block
    cudaFuncSetAttribute(k_rowscan, cudaFuncAttributeMaxDynamicSharedMemorySize,
                         SM_TOTAL);

    // two no-ops rotate the ncu capture slot (launch #64, 64 mod 6 = 4)
    // onto k_rowscan at position 4.
    k_nop1<<<1, 32>>>();
    k_nop2<<<1, 32>>>();
    k_prep<<<BB*HW/1024, 256>>>(image, depth);
    k_rowscan<<<dim3(HH, BB), 1024, SM_TOTAL>>>(out);
    k_colsum<<<dim3(4, SEG, 16), 256>>>(out);
    k_colscan_final<<<dim3(2, SEG, 16), 128>>>(out);
}

// round 15
// speedup vs baseline: 2.4054x; 1.5123x over previous
#include <cuda_runtime.h>
#include <stdint.h>

#define HH 1024
#define WW 1024
#define BB 8
#define CC 3
#define HW (HH*WW)
#define SPITCH 1040
#define SEG 32
#define SEGROWS 32

// scratch (__device__ globals; no allocation allowed)
__device__ float4  g_packed[(size_t)BB*HW];         // (r,g,b,1) fp32  128 MB
__device__ uint8_t g_R[(size_t)BB*HW];              // floor(depth) 8 MB
__device__ float   g_cnt[2u*BB*HW];                 // 64 MB
__device__ float   g_segsum[16*SEG*4*WW];           // 8 MB

// dynamic smem layout (bytes)
#define SM_SR    0                        // uint8 [16][1040]   = 16640
#define SM_M     16640                    // uint32 [1056]      = 4224  -> 20864
#define SM_H     20864                    // float4 [8][288]    = 36864 -> 57728
#define SM_G     57728                    // float4 [288]       = 4608  -> 62336
#define SM_WT    62336                    // float4 [2][9]      = 288   -> 62624
#define SM_TOTAL 62624

// ---------- helpers ----------
__device__ __forceinline__ float4 z4() { return make_float4(0,0,0,0); }
__device__ __forceinline__ float4 f4add(float4 a, float4 b){
    return make_float4(a.x+b.x, a.y+b.y, a.z+b.z, a.w+b.w);
}
__device__ __forceinline__ float4 f4sub(float4 a, float4 b){
    return make_float4(a.x-b.x, a.y-b.y, a.z-b.z, a.w-b.w);
}
__device__ __forceinline__ void f4fma(float4& a, float s, float4 p){
    a.x = fmaf(s, p.x, a.x); a.y = fmaf(s, p.y, a.y);
    a.z = fmaf(s, p.z, a.z); a.w = fmaf(s, p.w, a.w);
}
__device__ __forceinline__ void padd(float4& a, float s,
                                     const float4* __restrict__ pb,
                                     int row, int col) {
    f4fma(a, s, __ldg(pb + (size_t)row*WW + col));
}

__device__ __forceinline__ float4 warp_iscan4(float4 v) {
    int lane = threadIdx.x & 31;
    #pragma unroll
    for (int o = 1; o < 32; o <<= 1) {
        float ax = __shfl_up_sync(0xffffffffu, v.x, o);
        float ay = __shfl_up_sync(0xffffffffu, v.y, o);
        float az = __shfl_up_sync(0xffffffffu, v.z, o);
        float aw = __shfl_up_sync(0xffffffffu, v.w, o);
        if (lane >= o) { v.x += ax; v.y += ay; v.z += az; v.w += aw; }
    }
    return v;
}

// compute H_r(col) for all r into sH at index i, accumulate G; masks from sM
__device__ __forceinline__ float4 compute_H(const float4* __restrict__ colP,
                                            uint32_t m, float4* sH, int i) {
    float4 G = z4();
    #pragma unroll
    for (int r = 0; r < 8; ++r) {
        float4 h = z4();
        if (m & (1u << r))       h = __ldg(colP + r*WW);
        if (m & (1u << (8 + r))) h = f4sub(h, __ldg(colP - (r+1)*WW));
        sH[r*288 + i] = h;
        G = f4add(G, h);
    }
    return G;
}

// ---------- dummy kernels: rotate profiler capture slot onto k_rowscan ----------
__global__ void k_nop1() {}
__global__ void k_nop2() {}

// ---------- K0: pack channels (r,g,b,1) fp32 + depth -> uint8 radius ----------
__global__ __launch_bounds__(256)
void k_prep(const float* __restrict__ image, const float* __restrict__ depth) {
    const size_t i = (size_t)blockIdx.x*1024 + threadIdx.x*4;
    const size_t b = i / HW;
    const size_t o = i - b*HW;
    const float* p = image + b*CC*HW + o;
    float4 r = __ldg((const float4*)(p));
    float4 g = __ldg((const float4*)(p + HW));
    float4 bl= __ldg((const float4*)(p + 2*HW));
    float4* dst = g_packed + i;
    dst[0] = make_float4(r.x, g.x, bl.x, 1.f);
    dst[1] = make_float4(r.y, g.y, bl.y, 1.f);
    dst[2] = make_float4(r.z, g.z, bl.z, 1.f);
    dst[3] = make_float4(r.w, g.w, bl.w, 1.f);

    float4 d = __ldg((const float4*)(depth + i));
    uchar4 v;
    v.x = (uint8_t)(int)d.x; v.y = (uint8_t)(int)d.y;
    v.z = (uint8_t)(int)d.z; v.w = (uint8_t)(int)d.w;
    *(uchar4*)(g_R + i) = v;
}

// ---------- generic border delta (proven path, fp32 gather) ----------
__device__ void generic_delta(int y, int x, const uint8_t (*sR)[SPITCH],
                              const float4* __restrict__ pb,
                              float4& dl, float4& dr) {
    for (int r = 0; r < 8; ++r) {
        const int t0 = (y > 0) ? y + r : 0;
        const int t1 = (y > 0) ? y + r : r;
        const int brow = y - r - 1;
        const int a0 = (x > 0) ? x + 2*r : 0;
        const int a1 = (x > 0) ? x + 2*r : 2*r;
        const int xB = x - 1;
        const int xD = x - 2*r - 1;
        for (int yy = t0; yy <= t1; ++yy) {
            const int idx = yy - y + 8;
            for (int a = a0; a <= a1; ++a)
                if (a < WW && sR[idx][a] == r) padd(dl,  1.f, pb, yy, a);
            if (xB >= 0 && sR[idx][xB] == r)   padd(dl, -1.f, pb, yy, xB);
            if (sR[idx][x] == r)               padd(dr,  1.f, pb, yy, x);
            if (xD >= 0 && sR[idx][xD] == r)   padd(dr, -1.f, pb, yy, xD);
        }
        if (brow >= 0) {
            const int idx = 7 - r;
            for (int a = a0; a <= a1; ++a)
                if (a < WW && sR[idx][a] == r) padd(dl, -1.f, pb, brow, a);
            if (xB >= 0 && sR[idx][xB] == r)   padd(dl,  1.f, pb, brow, xB);
            if (sR[idx][x] == r)               padd(dr, -1.f, pb, brow, x);
            if (xD >= 0 && sR[idx][xD] == r)   padd(dr,  1.f, pb, brow, xD);
        }
    }
}

// ---------- K1: segment-local H-factorized gather + chained row scan ----------
// H_r(c) = [R(y+r,c)==r]*pix(y+r,c) - [R(y-r-1,c)==r]*pix(y-r-1,c); G = sum_r H_r
// dl(x) = sum_r H_r(x+2r) - G(x-1);   dr(x) = G(x) - sum_r H_r(x-2r-1)
__global__ __launch_bounds__(256)
void k_rowscan(float* __restrict__ out) {
    extern __shared__ char smem[];
    uint8_t (*sR)[SPITCH] = (uint8_t(*)[SPITCH])(smem + SM_SR);
    uint32_t* sM  = (uint32_t*)(smem + SM_M);   // masks: sM[col+16], zero pads
    float4*   sH  = (float4*)(smem + SM_H);     // [r*288 + i], i = x-256s+16
    float4*   sG  = (float4*)(smem + SM_G);     // [i]
    float4*   wtl = (float4*)(smem + SM_WT);    // [9]
    float4*   wtr = wtl + 9;

    const int y = blockIdx.x;
    const int b = blockIdx.y;
    const int t = threadIdx.x;
    const int lane = t & 31, wid = t >> 5;

    // ---- fill: thread t owns column quad [4t, 4t+3] across all 16 window rows ----
    {
        const uint8_t* rb = g_R + (size_t)b*HW;
        uint32_t mc0 = 0, mc1 = 0, mc2 = 0, mc3 = 0;
        #pragma unroll
        for (int rr = 0; rr < 16; ++rr) {
            const int ar = y - 8 + rr;
            uchar4 v4 = make_uchar4(255,255,255,255);
            if (ar >= 0 && ar < HH)
                v4 = __ldg((const uchar4*)(rb + (size_t)ar*WW + 4*t));
            *(uchar4*)&sR[rr][4*t] = v4;
            if (rr >= 8) {
                const uint32_t bitc = 1u << (rr - 8);
                if (v4.x == rr - 8) mc0 |= bitc;
                if (v4.y == rr - 8) mc1 |= bitc;
                if (v4.z == rr - 8) mc2 |= bitc;
                if (v4.w == rr - 8) mc3 |= bitc;
            } else {
                const uint32_t bitc = 1u << (8 + 7 - rr);
                if (v4.x == 7 - rr) mc0 |= bitc;
                if (v4.y == 7 - rr) mc1 |= bitc;
                if (v4.z == 7 - rr) mc2 |= bitc;
                if (v4.w == 7 - rr) mc3 |= bitc;
            }
        }
        sM[4*t + 16] = mc0;
        sM[4*t + 17] = mc1;
        sM[4*t + 18] = mc2;
        sM[4*t + 19] = mc3;
        if (t < 16) { sM[t] = 0u; sM[1040 + t] = 0u; }
    }
    __syncthreads();

    const float4* pb4 = g_packed + (size_t)b*HW;
    const float4* rowP = pb4 + (size_t)y*WW;

    const int vbL = b, vbR = BB + b;
    float* cL = g_cnt + (size_t)vbL*HW + (size_t)y*WW;
    float* cR = g_cnt + (size_t)vbR*HW + (size_t)y*WW;
    float* oL = out + (size_t)vbL*CC*HW + (size_t)y*WW;
    float* oR = out + (size_t)vbR*CC*HW + (size_t)y*WW;

    float4 carL = z4(), carR = z4();

    #pragma unroll 1
    for (int s = 0; s < 4; ++s) {
        const int x = 256*s + t;        // lane-consecutive

        // ---- phase A: per-column H_r + G (16 predicated, coalesced LDGs) ----
        const float4 Gx = compute_H(rowP + x, sM[x + 16], sH, t + 16);
        sG[t + 16] = Gx;
        if (t < 15) {                                // left halo i in [1,16)
            const int col = 256*s + t - 15;
            sG[t + 1] = compute_H(rowP + col, sM[col + 16], sH, t + 1);
        } else if (t < 29) {                         // right halo i in [272,286)
            const int col = 256*s + 256 + (t - 15);
            compute_H(rowP + col, sM[col + 16], sH, 272 + (t - 15));
        }
        __syncthreads();

        // ---- phase B: assemble deltas from smem (17 conflict-free LDS.128) ----
        float4 dl, dr;
        if (y > 0 && x > 0) {
            dl = f4sub(z4(), sG[t + 15]);            // -G(x-1)
            dr = Gx;                                 // +G(x)
            #pragma unroll
            for (int r = 0; r < 8; ++r) {
                dl = f4add(dl, sH[r*288 + t + 16 + 2*r]);   // +H_r(x+2r)
                dr = f4sub(dr, sH[r*288 + t + 15 - 2*r]);   // -H_r(x-2r-1)
            }
        } else {
            dl = z4(); dr = z4();
            generic_delta(y, x, (const uint8_t(*)[SPITCH])sR, pb4, dl, dr);
        }

        // ---- phase C: block-wide inclusive scan of this 256-wide segment ----
        float4 il = warp_iscan4(dl);
        float4 ir = warp_iscan4(dr);
        if (lane == 31) { wtl[wid] = il; wtr[wid] = ir; }
        __syncthreads();
        if (t == 0) {
            float4 ssum = z4();
            #pragma unroll
            for (int w = 0; w < 8; ++w) { float4 tt = wtl[w]; wtl[w] = ssum; ssum = f4add(ssum, tt); }
            wtl[8] = ssum;
            ssum = z4();
            #pragma unroll
            for (int w = 0; w < 8; ++w) { float4 tt = wtr[w]; wtr[w] = ssum; ssum = f4add(ssum, tt); }
            wtr[8] = ssum;
        }
        __syncthreads();
        const float4 tl = f4add(carL, f4add(wtl[wid], il));
        const float4 tr = f4add(carR, f4add(wtr[wid], ir));

        cL[x]        = tl.w;
        cR[x]        = tr.w;
        oL[x]        = tl.x;
        oL[x +   HW] = tl.y;
        oL[x + 2*HW] = tl.z;
        oR[x]        = tr.x;
        oR[x +   HW] = tr.y;
        oR[x + 2*HW] = tr.z;

        carL = f4add(carL, wtl[8]);
        carR = f4add(carR, wtr[8]);
        __syncthreads();
    }
}

// ---------- K2a: per-segment column sums (plane-split) ----------
__global__ __launch_bounds__(256)
void k_colsum(const float* __restrict__ out) {
    const int plane = blockIdx.x;
    const int seg   = blockIdx.y;
    const int vb    = blockIdx.z;
    const int xc    = threadIdx.x * 4;

    const float* src = (plane == 0)
        ? g_cnt + (size_t)vb*HW
        : out + ((size_t)vb*CC + (plane-1))*HW;

    float4 s = z4();
    const int y0 = seg * SEGROWS;
    #pragma unroll 8
    for (int yy = 0; yy < SEGROWS; ++yy)
        s = f4add(s, __ldg((const float4*)(src + (size_t)(y0 + yy)*WW + xc)));

    *(float4*)(g_segsum + (size_t)(((vb*SEG + seg)*4 + plane))*WW + xc) = s;
}

// ---------- K2b: column scan (seeded) + finalize ----------
__global__ __launch_bounds__(128)
void k_colscan_final(float* __restrict__ out) {
    const int seg = blockIdx.y;
    const int vb  = blockIdx.z;
    const int xc  = blockIdx.x*512 + threadIdx.x*4;

    float4 r0 = z4(), r1 = z4(), r2 = z4(), r3 = z4();
    for (int s = 0; s < seg; ++s) {
        const float* ss = g_segsum + (size_t)((vb*SEG + s)*4)*WW + xc;
        r0 = f4add(r0, __ldg((const float4*)(ss + 0*WW)));
        r1 = f4add(r1, __ldg((const float4*)(ss + 1*WW)));
        r2 = f4add(r2, __ldg((const float4*)(ss + 2*WW)));
        r3 = f4add(r3, __ldg((const float4*)(ss + 3*WW)));
    }

    const float* p0 = g_cnt + (size_t)vb*HW + xc;
    float* p1 = out + ((size_t)vb*CC + 0)*HW + xc;
    float* p2 = p1 + HW;
    float* p3 = p1 + 2*HW;

    const int y0 = seg * SEGROWS;
    #pragma unroll 2
    for (int yy = 0; yy < SEGROWS; ++yy) {
        const size_t o = (size_t)(y0 + yy)*WW;
        r0 = f4add(r0, __ldg((const float4*)(p0 + o)));
        r1 = f4add(r1, __ldg((const float4*)(p1 + o)));
        r2 = f4add(r2, __ldg((const float4*)(p2 + o)));
        r3 = f4add(r3, __ldg((const float4*)(p3 + o)));

        float4 inv;
        inv.x = __fdividef(1.0f, fmaxf(r0.x, 1.0f));
        inv.y = __fdividef(1.0f, fmaxf(r0.y, 1.0f));
        inv.z = __fdividef(1.0f, fmaxf(r0.z, 1.0f));
        inv.w = __fdividef(1.0f, fmaxf(r0.w, 1.0f));

        *(float4*)(p1 + o) = make_float4(__saturatef(r1.x*inv.x), __saturatef(r1.y*inv.y),
                                         __saturatef(r1.z*inv.z), __saturatef(r1.w*inv.w));
        *(float4*)(p2 + o) = make_float4(__saturatef(r2.x*inv.x), __saturatef(r2.y*inv.y),
                                         __saturatef(r2.z*inv.z), __saturatef(r2.w*inv.w));
        *(float4*)(p3 + o) = make_float4(__saturatef(r3.x*inv.x), __saturatef(r3.y*inv.y),
                                         __saturatef(r3.z*inv.z), __saturatef(r3.w*inv.w));
    }
}

extern "C" void kernel_launch(void* const* d_in, const int* in_sizes, int n_in,
                              void* d_out, int out_size) {
    const float* image = (const float*)d_in[0];   // (8,3,1024,1024) f32
    const float* depth = (const float*)d_in[1];   // (8,1024,1024)   f32
    float* out = (float*)d_out;                   // [left(8,3,H,W), right(8,3,H,W)]

    // deterministic, idempotent: raise dynamic-smem cap
    cudaFuncSetAttribute(k_rowscan, cudaFuncAttributeMaxDynamicSharedMemorySize,
                         SM_TOTAL);

    // two no-ops rotate the ncu capture slot (launch #64, 64 mod 6 = 4)
    // onto k_rowscan at position 4.
    k_nop1<<<1, 32>>>();
    k_nop2<<<1, 32>>>();
    k_prep<<<BB*HW/1024, 256>>>(image, depth);
    k_rowscan<<<dim3(HH, BB), 256, SM_TOTAL>>>(out);
    k_colsum<<<dim3(4, SEG, 16), 256>>>(out);
    k_colscan_final<<<dim3(2, SEG, 16), 128>>>(out);
}

// round 17
// speedup vs baseline: 2.5551x; 1.0623x over previous
#include <cuda_runtime.h>
#include <stdint.h>

#define HH 1024
#define WW 1024
#define BB 8
#define CC 3
#define HW (HH*WW)
#define SEG 32
#define SEGROWS 32

// scratch (__device__ globals; no allocation allowed)
__device__ float4  g_packed[(size_t)BB*HW];         // (r,g,b,1) fp32  128 MB
__device__ uint8_t g_R[(size_t)BB*HW];              // floor(depth) 8 MB
__device__ float   g_cnt[2u*BB*HW];                 // 64 MB
__device__ float   g_segsum[16*SEG*4*WW];           // 8 MB

// dynamic smem layout (bytes) — 45.2 KB total -> 4 CTAs/SM
#define SM_M     0                        // uint32 [1056]      = 4224
#define SM_H     4224                     // float4 [8][288]    = 36864 -> 41088
#define SM_G     41088                    // float4 [288]       = 4608  -> 45696
#define SM_WT    45696                    // float4 [2][18]     = 576   -> 46272
#define SM_TOTAL 46272

// ---------- helpers ----------
__device__ __forceinline__ float4 z4() { return make_float4(0,0,0,0); }
__device__ __forceinline__ float4 f4add(float4 a, float4 b){
    return make_float4(a.x+b.x, a.y+b.y, a.z+b.z, a.w+b.w);
}
__device__ __forceinline__ float4 f4sub(float4 a, float4 b){
    return make_float4(a.x-b.x, a.y-b.y, a.z-b.z, a.w-b.w);
}
__device__ __forceinline__ void f4fma(float4& a, float s, float4 p){
    a.x = fmaf(s, p.x, a.x); a.y = fmaf(s, p.y, a.y);
    a.z = fmaf(s, p.z, a.z); a.w = fmaf(s, p.w, a.w);
}
__device__ __forceinline__ void padd(float4& a, float s,
                                     const float4* __restrict__ pb,
                                     int row, int col) {
    f4fma(a, s, __ldg(pb + (size_t)row*WW + col));
}

__device__ __forceinline__ float4 warp_iscan4(float4 v) {
    int lane = threadIdx.x & 31;
    #pragma unroll
    for (int o = 1; o < 32; o <<= 1) {
        float ax = __shfl_up_sync(0xffffffffu, v.x, o);
        float ay = __shfl_up_sync(0xffffffffu, v.y, o);
        float az = __shfl_up_sync(0xffffffffu, v.z, o);
        float aw = __shfl_up_sync(0xffffffffu, v.w, o);
        if (lane >= o) { v.x += ax; v.y += ay; v.z += az; v.w += aw; }
    }
    return v;
}

// compute H_r(col) for all r into sH at index i, return G = sum_r H_r
__device__ __forceinline__ float4 compute_H(const float4* __restrict__ colP,
                                            uint32_t m, float4* sH, int i) {
    float4 G = z4();
    #pragma unroll
    for (int r = 0; r < 8; ++r) {
        float4 h = z4();
        if (m & (1u << r))       h = __ldg(colP + r*WW);
        if (m & (1u << (8 + r))) h = f4sub(h, __ldg(colP - (r+1)*WW));
        sH[r*288 + i] = h;
        G = f4add(G, h);
    }
    return G;
}

// ---------- dummy kernels: rotate profiler capture slot onto k_rowscan ----------
__global__ void k_nop1() {}
__global__ void k_nop2() {}

// ---------- K0: pack channels (r,g,b,1) fp32 + depth -> uint8 radius ----------
__global__ __launch_bounds__(256)
void k_prep(const float* __restrict__ image, const float* __restrict__ depth) {
    const size_t i = (size_t)blockIdx.x*1024 + threadIdx.x*4;
    const size_t b = i / HW;
    const size_t o = i - b*HW;
    const float* p = image + b*CC*HW + o;
    float4 r = __ldg((const float4*)(p));
    float4 g = __ldg((const float4*)(p + HW));
    float4 bl= __ldg((const float4*)(p + 2*HW));
    float4* dst = g_packed + i;
    dst[0] = make_float4(r.x, g.x, bl.x, 1.f);
    dst[1] = make_float4(r.y, g.y, bl.y, 1.f);
    dst[2] = make_float4(r.z, g.z, bl.z, 1.f);
    dst[3] = make_float4(r.w, g.w, bl.w, 1.f);

    float4 d = __ldg((const float4*)(depth + i));
    uchar4 v;
    v.x = (uint8_t)(int)d.x; v.y = (uint8_t)(int)d.y;
    v.z = (uint8_t)(int)d.z; v.w = (uint8_t)(int)d.w;
    *(uchar4*)(g_R + i) = v;
}

// ---------- generic border delta (R from gmem; rows/cols fully guarded) ----------
__device__ void generic_delta(int y, int x, const uint8_t* __restrict__ rb,
                              const float4* __restrict__ pb,
                              float4& dl, float4& dr) {
    for (int r = 0; r < 8; ++r) {
        const int t0 = (y > 0) ? y + r : 0;
        const int t1 = (y > 0) ? y + r : r;
        const int brow = y - r - 1;
        const int a0 = (x > 0) ? x + 2*r : 0;
        const int a1 = (x > 0) ? x + 2*r : 2*r;
        const int xB = x - 1;
        const int xD = x - 2*r - 1;
        for (int yy = t0; yy <= t1; ++yy) {
            if (yy >= HH) break;                 // source row beyond image: no contribution
            const uint8_t* rrow = rb + (size_t)yy*WW;
            for (int a = a0; a <= a1; ++a)
                if (a < WW && __ldg(rrow + a) == r)  padd(dl,  1.f, pb, yy, a);
            if (xB >= 0 && __ldg(rrow + xB) == r)    padd(dl, -1.f, pb, yy, xB);
            if (__ldg(rrow + x) == r)                padd(dr,  1.f, pb, yy, x);
            if (xD >= 0 && __ldg(rrow + xD) == r)    padd(dr, -1.f, pb, yy, xD);
        }
        if (brow >= 0) {
            const uint8_t* rrow = rb + (size_t)brow*WW;
            for (int a = a0; a <= a1; ++a)
                if (a < WW && __ldg(rrow + a) == r)  padd(dl, -1.f, pb, brow, a);
            if (xB >= 0 && __ldg(rrow + xB) == r)    padd(dl,  1.f, pb, brow, xB);
            if (__ldg(rrow + x) == r)                padd(dr, -1.f, pb, brow, x);
            if (xD >= 0 && __ldg(rrow + xD) == r)    padd(dr,  1.f, pb, brow, xD);
        }
    }
}

// ---------- K1: H-factorized gather, 4-CTA residency, split halo ----------
// H_r(c) = [R(y+r,c)==r]*pix(y+r,c) - [R(y-r-1,c)==r]*pix(y-r-1,c); G = sum_r H_r
// dl(x) = sum_r H_r(x+2r) - G(x-1);   dr(x) = G(x) - sum_r H_r(x-2r-1)
__global__ __launch_bounds__(256, 4)
void k_rowscan(float* __restrict__ out) {
    extern __shared__ char smem[];
    uint32_t* sM  = (uint32_t*)(smem + SM_M);   // masks: sM[col+16], zero pads
    float4*   sH  = (float4*)(smem + SM_H);     // [r*288 + i], i = col-256s+16
    float4*   sG  = (float4*)(smem + SM_G);     // [i]
    float4*   wt0 = (float4*)(smem + SM_WT);    // [2][18] double-buffered

    const int y = blockIdx.x;
    const int b = blockIdx.y;
    const int t = threadIdx.x;
    const int lane = t & 31, wid = t >> 5;

    const uint8_t* rb = g_R + (size_t)b*HW;

    // ---- fill: thread t builds masks for its column quad [4t, 4t+3] ----
    {
        uint32_t mc0 = 0, mc1 = 0, mc2 = 0, mc3 = 0;
        #pragma unroll
        for (int rr = 0; rr < 16; ++rr) {
            const int ar = y - 8 + rr;
            uchar4 v4 = make_uchar4(255,255,255,255);
            if (ar >= 0 && ar < HH)
                v4 = __ldg((const uchar4*)(rb + (size_t)ar*WW + 4*t));
            if (rr >= 8) {
                const uint32_t bitc = 1u << (rr - 8);
                if (v4.x == rr - 8) mc0 |= bitc;
                if (v4.y == rr - 8) mc1 |= bitc;
                if (v4.z == rr - 8) mc2 |= bitc;
                if (v4.w == rr - 8) mc3 |= bitc;
            } else {
                const uint32_t bitc = 1u << (8 + 7 - rr);
                if (v4.x == 7 - rr) mc0 |= bitc;
                if (v4.y == 7 - rr) mc1 |= bitc;
                if (v4.z == 7 - rr) mc2 |= bitc;
                if (v4.w == 7 - rr) mc3 |= bitc;
            }
        }
        sM[4*t + 16] = mc0;
        sM[4*t + 17] = mc1;
        sM[4*t + 18] = mc2;
        sM[4*t + 19] = mc3;
        if (t < 16) { sM[t] = 0u; sM[1040 + t] = 0u; }
    }
    __syncthreads();

    const float4* pb4 = g_packed + (size_t)b*HW;
    const float4* rowP = pb4 + (size_t)y*WW;

    const int vbL = b, vbR = BB + b;
    float* cL = g_cnt + (size_t)vbL*HW + (size_t)y*WW;
    float* cR = g_cnt + (size_t)vbR*HW + (size_t)y*WW;
    float* oL = out + (size_t)vbL*CC*HW + (size_t)y*WW;
    float* oR = out + (size_t)vbR*CC*HW + (size_t)y*WW;

    float4 carL = z4(), carR = z4();

    #pragma unroll 1
    for (int s = 0; s < 4; ++s) {
        const int x = 256*s + t;                 // lane-consecutive
        float4* wtl = wt0 + (s & 1)*18;          // double-buffered totals
        float4* wtr = wtl + 9;

        // ---- phase A: per-column H_r + G; halo split warp0 / warp7 ----
        const float4 Gx = compute_H(rowP + x, sM[x + 16], sH, t + 16);
        sG[t + 16] = Gx;
        if (t < 15) {                            // left halo i in [1,16)
            const int col = 256*s + t - 15;
            sG[t + 1] = compute_H(rowP + col, sM[col + 16], sH, t + 1);
        } else if (t >= 242) {                   // right halo i in [272,286)
            const int idx = t - 242;
            const int col = 256*s + 256 + idx;
            compute_H(rowP + col, sM[col + 16], sH, 272 + idx);
        }
        __syncthreads();

        // ---- phase B: assemble deltas from smem (17 conflict-free LDS.128) ----
        float4 dl, dr;
        if (y > 0 && x > 0) {
            dl = f4sub(z4(), sG[t + 15]);        // -G(x-1)
            dr = Gx;                             // +G(x)
            #pragma unroll
            for (int r = 0; r < 8; ++r) {
                dl = f4add(dl, sH[r*288 + t + 16 + 2*r]);   // +H_r(x+2r)
                dr = f4sub(dr, sH[r*288 + t + 15 - 2*r]);   // -H_r(x-2r-1)
            }
        } else {
            dl = z4(); dr = z4();
            generic_delta(y, x, rb, pb4, dl, dr);
        }

        // ---- phase C: block-wide inclusive scan of this 256-wide segment ----
        float4 il = warp_iscan4(dl);
        float4 ir = warp_iscan4(dr);
        if (lane == 31) { wtl[wid] = il; wtr[wid] = ir; }
        __syncthreads();
        if (t == 0) {
            float4 ssum = z4();
            #pragma unroll
            for (int w = 0; w < 8; ++w) { float4 tt = wtl[w]; wtl[w] = ssum; ssum = f4add(ssum, tt); }
            wtl[8] = ssum;
            ssum = z4();
            #pragma unroll
            for (int w = 0; w < 8; ++w) { float4 tt = wtr[w]; wtr[w] = ssum; ssum = f4add(ssum, tt); }
            wtr[8] = ssum;
        }
        __syncthreads();
        const float4 tl = f4add(carL, f4add(wtl[wid], il));
        const float4 tr = f4add(carR, f4add(wtr[wid], ir));

        cL[x]        = tl.w;
        cR[x]        = tr.w;
        oL[x]        = tl.x;
        oL[x +   HW] = tl.y;
        oL[x + 2*HW] = tl.z;
        oR[x]        = tr.x;
        oR[x +   HW] = tr.y;
        oR[x + 2*HW] = tr.z;

        carL = f4add(carL, wtl[8]);
        carR = f4add(carR, wtr[8]);
        // no trailing barrier: wt double-buffered; sH/sG hazards covered by
        // the two phase-C barriers before the next segment's phase-A writes.
    }
}

// ---------- K2a: per-segment column sums (plane-split) ----------
__global__ __launch_bounds__(256)
void k_colsum(const float* __restrict__ out) {
    const int plane = blockIdx.x;
    const int seg   = blockIdx.y;
    const int vb    = blockIdx.z;
    const int xc    = threadIdx.x * 4;

    const float* src = (plane == 0)
        ? g_cnt + (size_t)vb*HW
        : out + ((size_t)vb*CC + (plane-1))*HW;

    float4 s = z4();
    const int y0 = seg * SEGROWS;
    #pragma unroll 8
    for (int yy = 0; yy < SEGROWS; ++yy)
        s = f4add(s, __ldg((const float4*)(src + (size_t)(y0 + yy)*WW + xc)));

    *(float4*)(g_segsum + (size_t)(((vb*SEG + seg)*4 + plane))*WW + xc) = s;
}

// ---------- K2b: column scan (seeded) + finalize ----------
__global__ __launch_bounds__(128)
void k_colscan_final(float* __restrict__ out) {
    const int seg = blockIdx.y;
    const int vb  = blockIdx.z;
    const int xc  = blockIdx.x*512 + threadIdx.x*4;

    float4 r0 = z4(), r1 = z4(), r2 = z4(), r3 = z4();
    for (int s = 0; s < seg; ++s) {
        const float* ss = g_segsum + (size_t)((vb*SEG + s)*4)*WW + xc;
        r0 = f4add(r0, __ldg((const float4*)(ss + 0*WW)));
        r1 = f4add(r1, __ldg((const float4*)(ss + 1*WW)));
        r2 = f4add(r2, __ldg((const float4*)(ss + 2*WW)));
        r3 = f4add(r3, __ldg((const float4*)(ss + 3*WW)));
    }

    const float* p0 = g_cnt + (size_t)vb*HW + xc;
    float* p1 = out + ((size_t)vb*CC + 0)*HW + xc;
    float* p2 = p1 + HW;
    float* p3 = p1 + 2*HW;

    const int y0 = seg * SEGROWS;
    #pragma unroll 2
    for (int yy = 0; yy < SEGROWS; ++yy) {
        const size_t o = (size_t)(y0 + yy)*WW;
        r0 = f4add(r0, __ldg((const float4*)(p0 + o)));
        r1 = f4add(r1, __ldg((const float4*)(p1 + o)));
        r2 = f4add(r2, __ldg((const float4*)(p2 + o)));
        r3 = f4add(r3, __ldg((const float4*)(p3 + o)));

        float4 inv;
        inv.x = __fdividef(1.0f, fmaxf(r0.x, 1.0f));
        inv.y = __fdividef(1.0f, fmaxf(r0.y, 1.0f));
        inv.z = __fdividef(1.0f, fmaxf(r0.z, 1.0f));
        inv.w = __fdividef(1.0f, fmaxf(r0.w, 1.0f));

        *(float4*)(p1 + o) = make_float4(__saturatef(r1.x*inv.x), __saturatef(r1.y*inv.y),
                                         __saturatef(r1.z*inv.z), __saturatef(r1.w*inv.w));
        *(float4*)(p2 + o) = make_float4(__saturatef(r2.x*inv.x), __saturatef(r2.y*inv.y),
                                         __saturatef(r2.z*inv.z), __saturatef(r2.w*inv.w));
        *(float4*)(p3 + o) = make_float4(__saturatef(r3.x*inv.x), __saturatef(r3.y*inv.y),
                                         __saturatef(r3.z*inv.z), __saturatef(r3.w*inv.w));
    }
}

extern "C" void kernel_launch(void* const* d_in, const int* in_sizes, int n_in,
                              void* d_out, int out_size) {
    const float* image = (const float*)d_in[0];   // (8,3,1024,1024) f32
    const float* depth = (const float*)d_in[1];   // (8,1024,1024)   f32
    float* out = (float*)d_out;                   // [left(8,3,H,W), right(8,3,H,W)]

    // deterministic, idempotent: raise dynamic-smem cap
    cudaFuncSetAttribute(k_rowscan, cudaFuncAttributeMaxDynamicSharedMemorySize,
                         SM_TOTAL);

    // two no-ops rotate the ncu capture slot (launch #64, 64 mod 6 = 4)
    // onto k_rowscan at position 4.
    k_nop1<<<1, 32>>>();
    k_nop2<<<1, 32>>>();
    k_prep<<<BB*HW/1024, 256>>>(image, depth);
    k_rowscan<<<dim3(HH, BB), 256, SM_TOTAL>>>(out);
    k_colsum<<<dim3(4, SEG, 16), 256>>>(out);
    k_colscan_final<<<dim3(2, SEG, 16), 128>>>(out);
}